// round 1
// baseline (speedup 1.0000x reference)
#include <cuda_runtime.h>

#define Bsz 16384
#define Cn  8
#define Dd  256
#define H0n 512
#define H1n 256

#define TM       64
#define NTHREADS 256

// shared memory layout (float offsets)
#define XS_PITCH  68            // x transposed [Dd][68]
#define XS_OFF    0
#define H0S_PITCH 516           // h0 row-major [64][516]
#define H0S_OFF   (Dd * XS_PITCH)                    // 17408
#define WT_PITCH  260           // W tile transposed [16][260]
#define WT_OFF    (H0S_OFF + TM * H0S_PITCH)         // 50432
#define B0S_OFF   (WT_OFF + 16 * WT_PITCH)           // 54592
#define B1S_OFF   (B0S_OFF + H0n)                    // 55104
#define W2S_OFF   (B1S_OFF + H1n)                    // 55360
#define OUTS_OFF  (W2S_OFF + H1n)                    // 55616
#define SMEM_FLOATS (OUTS_OFF + TM)                  // 55680 -> 222720 B

typedef unsigned long long u64;

__device__ __forceinline__ u64 pack2(float lo, float hi) {
    u64 r; asm("mov.b64 %0, {%1, %2};" : "=l"(r) : "f"(lo), "f"(hi)); return r;
}
__device__ __forceinline__ void unpack2(u64 v, float &lo, float &hi) {
    asm("mov.b64 {%0, %1}, %2;" : "=f"(lo), "=f"(hi) : "l"(v));
}
// packed dual FMA: d.lo += a.lo*b.lo ; d.hi += a.hi*b.hi
__device__ __forceinline__ void ffma2(u64 &d, u64 a, u64 b) {
    asm("fma.rn.f32x2 %0, %1, %2, %0;" : "+l"(d) : "l"(a), "l"(b));
}

// ---- W tile load (global -> regs) and store (regs -> smem transposed) ----
#define LOADW(Wc, Kdim, nbase, kbase) do {                                   \
    const float* _p = (Wc) + (size_t)((nbase) + nl) * (Kdim) + (kbase) + kq * 4; \
    p0 = *(const float4*)(_p);                                               \
    p1 = *(const float4*)(_p + (size_t)64  * (Kdim));                        \
    p2 = *(const float4*)(_p + (size_t)128 * (Kdim));                        \
    p3 = *(const float4*)(_p + (size_t)192 * (Kdim));                        \
} while (0)

#define STSW() do {                                                          \
    float* _w = wt + (kq * 4) * WT_PITCH + nl;                               \
    _w[0*WT_PITCH +   0] = p0.x; _w[1*WT_PITCH +   0] = p0.y;                \
    _w[2*WT_PITCH +   0] = p0.z; _w[3*WT_PITCH +   0] = p0.w;                \
    _w[0*WT_PITCH +  64] = p1.x; _w[1*WT_PITCH +  64] = p1.y;                \
    _w[2*WT_PITCH +  64] = p1.z; _w[3*WT_PITCH +  64] = p1.w;                \
    _w[0*WT_PITCH + 128] = p2.x; _w[1*WT_PITCH + 128] = p2.y;                \
    _w[2*WT_PITCH + 128] = p2.z; _w[3*WT_PITCH + 128] = p2.w;                \
    _w[0*WT_PITCH + 192] = p3.x; _w[1*WT_PITCH + 192] = p3.y;                \
    _w[2*WT_PITCH + 192] = p3.z; _w[3*WT_PITCH + 192] = p3.w;                \
} while (0)

// one k-slice of the 4x16 microtile given packed a0..a3
#define MICRO_FMA(k2)                                                        \
    _Pragma("unroll")                                                        \
    for (int cc = 0; cc < 4; cc++) {                                         \
        const float4 bv = *(const float4*)(wt + (k2) * WT_PITCH + cc * 64 + tx * 4); \
        u64 bA = pack2(bv.x, bv.y);                                          \
        u64 bB = pack2(bv.z, bv.w);                                          \
        ffma2(acc[0*8 + cc*2 + 0], a0, bA); ffma2(acc[0*8 + cc*2 + 1], a0, bB); \
        ffma2(acc[1*8 + cc*2 + 0], a1, bA); ffma2(acc[1*8 + cc*2 + 1], a1, bB); \
        ffma2(acc[2*8 + cc*2 + 0], a2, bA); ffma2(acc[2*8 + cc*2 + 1], a2, bB); \
        ffma2(acc[3*8 + cc*2 + 0], a3, bA); ffma2(acc[3*8 + cc*2 + 1], a3, bB); \
    }

__global__ void __launch_bounds__(NTHREADS, 1)
confounder_fused_kernel(const float* __restrict__ x,
                        const float* __restrict__ W0,
                        const float* __restrict__ b0,
                        const float* __restrict__ W1,
                        const float* __restrict__ b1,
                        const float* __restrict__ W2,
                        const float* __restrict__ b2,
                        float* __restrict__ out)
{
    extern __shared__ float sm[];
    const int tid  = threadIdx.x;
    const int tx   = tid & 15;
    const int ty   = tid >> 4;
    const int row0 = blockIdx.x * TM;
    const int c    = blockIdx.y;

    const int kq = tid & 3;     // k quad within 16-k tile
    const int nl = tid >> 2;    // n lane 0..63

    float* xs   = sm + XS_OFF;
    float* h0s  = sm + H0S_OFF;
    float* wt   = sm + WT_OFF;
    float* b0s  = sm + B0S_OFF;
    float* b1s  = sm + B1S_OFF;
    float* w2s  = sm + W2S_OFF;
    float* outs = sm + OUTS_OFF;

    // ---- preamble: biases, w2, zero out accumulator, x tile (transposed) ----
    for (int i = tid; i < H0n; i += NTHREADS) b0s[i] = b0[c * H0n + i];
    for (int i = tid; i < H1n; i += NTHREADS) b1s[i] = b1[c * H1n + i];
    for (int i = tid; i < H1n; i += NTHREADS) w2s[i] = W2[c * H1n + i];
    if (tid < TM) outs[tid] = 0.0f;

    {
        const int row = tid & 63;
        const int cg0 = tid >> 6;   // 0..3
        #pragma unroll
        for (int i = 0; i < 16; i++) {
            const int c4 = cg0 + i * 4;   // 0..63
            const float4 v = *(const float4*)(x + (size_t)(row0 + row) * Dd + c4 * 4);
            xs[(c4 * 4 + 0) * XS_PITCH + row] = v.x;
            xs[(c4 * 4 + 1) * XS_PITCH + row] = v.y;
            xs[(c4 * 4 + 2) * XS_PITCH + row] = v.z;
            xs[(c4 * 4 + 3) * XS_PITCH + row] = v.w;
        }
    }

    float4 p0, p1, p2, p3;

    // =================== Layer 0: h0 = relu(x @ W0[c]^T + b0) ===================
    {
        const float* Wc = W0 + (size_t)c * H0n * Dd;
        #pragma unroll 1
        for (int nn = 0; nn < 2; nn++) {
            const int nbase = nn * 256;
            u64 acc[32];
            #pragma unroll
            for (int q = 0; q < 32; q++) acc[q] = 0ULL;

            LOADW(Wc, Dd, nbase, 0);
            __syncthreads();            // wt free of previous readers; xs/bias visible
            STSW();
            __syncthreads();

            const int NK = Dd / 16;     // 16
            #pragma unroll 1
            for (int kk = 0; kk < NK; kk++) {
                if (kk + 1 < NK) LOADW(Wc, Dd, nbase, (kk + 1) * 16);
                const int kbase = kk * 16;
                #pragma unroll
                for (int k2 = 0; k2 < 16; k2++) {
                    const float4 av = *(const float4*)(xs + (kbase + k2) * XS_PITCH + ty * 4);
                    u64 a0 = pack2(av.x, av.x);
                    u64 a1 = pack2(av.y, av.y);
                    u64 a2 = pack2(av.z, av.z);
                    u64 a3 = pack2(av.w, av.w);
                    MICRO_FMA(k2)
                }
                if (kk + 1 < NK) { __syncthreads(); STSW(); __syncthreads(); }
            }

            // epilogue: bias + relu -> h0s (row-major)
            #pragma unroll
            for (int i = 0; i < 4; i++) {
                const int m = ty * 4 + i;
                #pragma unroll
                for (int cc = 0; cc < 4; cc++) {
                    float e0, e1, e2, e3;
                    unpack2(acc[i*8 + cc*2 + 0], e0, e1);
                    unpack2(acc[i*8 + cc*2 + 1], e2, e3);
                    const int n = nbase + cc * 64 + tx * 4;
                    float4 o;
                    o.x = fmaxf(e0 + b0s[n + 0], 0.0f);
                    o.y = fmaxf(e1 + b0s[n + 1], 0.0f);
                    o.z = fmaxf(e2 + b0s[n + 2], 0.0f);
                    o.w = fmaxf(e3 + b0s[n + 3], 0.0f);
                    *(float4*)(h0s + m * H0S_PITCH + n) = o;
                }
            }
        }
    }

    // =================== Layer 1 + head: out = relu(h0 @ W1^T + b1) . w2 + b2 ===================
    {
        const float* Wc = W1 + (size_t)c * H1n * H0n;
        u64 acc[32];
        #pragma unroll
        for (int q = 0; q < 32; q++) acc[q] = 0ULL;

        LOADW(Wc, H0n, 0, 0);
        __syncthreads();            // h0s complete + wt free
        STSW();
        __syncthreads();

        const int NK = H0n / 16;    // 32
        #pragma unroll 1
        for (int kk = 0; kk < NK; kk++) {
            if (kk + 1 < NK) LOADW(Wc, H0n, 0, (kk + 1) * 16);
            const int kbase = kk * 16;
            #pragma unroll
            for (int k2 = 0; k2 < 16; k2++) {
                const int kg = kbase + k2;
                const float v0 = h0s[(ty * 4 + 0) * H0S_PITCH + kg];
                const float v1 = h0s[(ty * 4 + 1) * H0S_PITCH + kg];
                const float v2 = h0s[(ty * 4 + 2) * H0S_PITCH + kg];
                const float v3 = h0s[(ty * 4 + 3) * H0S_PITCH + kg];
                u64 a0 = pack2(v0, v0);
                u64 a1 = pack2(v1, v1);
                u64 a2 = pack2(v2, v2);
                u64 a3 = pack2(v3, v3);
                MICRO_FMA(k2)
            }
            if (kk + 1 < NK) { __syncthreads(); STSW(); __syncthreads(); }
        }

        // epilogue: bias + relu, dot with w2, reduce into outs
        #pragma unroll
        for (int i = 0; i < 4; i++) {
            float s = 0.0f;
            #pragma unroll
            for (int cc = 0; cc < 4; cc++) {
                float e0, e1, e2, e3;
                unpack2(acc[i*8 + cc*2 + 0], e0, e1);
                unpack2(acc[i*8 + cc*2 + 1], e2, e3);
                const int n = cc * 64 + tx * 4;
                s += fmaxf(e0 + b1s[n + 0], 0.0f) * w2s[n + 0];
                s += fmaxf(e1 + b1s[n + 1], 0.0f) * w2s[n + 1];
                s += fmaxf(e2 + b1s[n + 2], 0.0f) * w2s[n + 2];
                s += fmaxf(e3 + b1s[n + 3], 0.0f) * w2s[n + 3];
            }
            atomicAdd(&outs[ty * 4 + i], s);
        }
    }

    __syncthreads();
    if (tid < TM) {
        out[(size_t)(row0 + tid) * Cn + c] = outs[tid] + b2[c];
    }
}

extern "C" void kernel_launch(void* const* d_in, const int* in_sizes, int n_in,
                              void* d_out, int out_size) {
    (void)in_sizes; (void)n_in; (void)out_size;
    const float* x  = (const float*)d_in[0];
    const float* W0 = (const float*)d_in[1];
    const float* b0 = (const float*)d_in[2];
    const float* W1 = (const float*)d_in[3];
    const float* b1 = (const float*)d_in[4];
    const float* W2 = (const float*)d_in[5];
    const float* b2 = (const float*)d_in[6];
    float* out = (float*)d_out;

    cudaFuncSetAttribute(confounder_fused_kernel,
                         cudaFuncAttributeMaxDynamicSharedMemorySize,
                         SMEM_FLOATS * sizeof(float));

    dim3 grid(Bsz / TM, Cn);
    confounder_fused_kernel<<<grid, NTHREADS, SMEM_FLOATS * sizeof(float)>>>(
        x, W0, b0, W1, b1, W2, b2, out);
}